// round 1
// baseline (speedup 1.0000x reference)
#include <cuda_runtime.h>
#include <math.h>

// Problem constants
constexpr int Bb   = 2;
constexpr int Hh   = 16;
constexpr int Nn   = 2048;
constexpr int HDc  = 64;
constexpr int DIMd = 1024;
constexpr int Mrows = Bb * Nn;       // 4096
constexpr float ATTN_SCALE = 0.125f; // 64^-0.5

// Scratch: [B, H, N, HD] split-head layouts (16 MB each)
__device__ float g_qh[Bb * Hh * Nn * HDc];
__device__ float g_kh[Bb * Hh * Nn * HDc];
__device__ float g_vh[Bb * Hh * Nn * HDc];
__device__ float g_ao[Bb * Hh * Nn * HDc];

__device__ __forceinline__ float f4c(const float4& v, int u) {
    return u == 0 ? v.x : (u == 1 ? v.y : (u == 2 ? v.z : v.w));
}

// ---------------------------------------------------------------------------
// Projection GEMM: C[m,n] = sum_k A[m,k] * W[n,k] + bias[n]
// A logical [4096,1024]. If SPLIT_IN, A physically [B,H,N,64] (merge-heads
// gather in the load). If SPLIT_OUT, C written as [B,H,N,64] (split-heads
// scatter in the epilogue), else plain [4096,1024].
// 128x128 block tile, TK=8, 256 threads, 8x8 micro-tile.
// ---------------------------------------------------------------------------
template <bool SPLIT_IN, bool SPLIT_OUT>
__global__ __launch_bounds__(256) void proj_gemm(
    const float* __restrict__ A, const float* __restrict__ W,
    const float* __restrict__ bias, float* __restrict__ C)
{
    __shared__ float As[8][128];
    __shared__ float Bs[8][128];

    const int m0 = blockIdx.y * 128;
    const int n0 = blockIdx.x * 128;
    const int tid = threadIdx.x;
    const int tx = tid & 15;      // 0..15 (n dim)
    const int ty = tid >> 4;      // 0..15 (m dim)
    const int lr = tid >> 1;      // 0..127 (row for loads)
    const int lk = (tid & 1) << 2; // 0 or 4 (k offset for loads)

    float acc[8][8];
#pragma unroll
    for (int i = 0; i < 8; i++)
#pragma unroll
        for (int j = 0; j < 8; j++) acc[i][j] = 0.f;

    for (int k0 = 0; k0 < DIMd; k0 += 8) {
        const int gm = m0 + lr;
        const int gk = k0 + lk;
        const float* ap;
        if (SPLIT_IN) {
            const int b = gm >> 11, tok = gm & (Nn - 1);
            const int h = gk >> 6, c = gk & 63;
            ap = A + ((size_t)((b * Hh + h) * Nn + tok)) * HDc + c;
        } else {
            ap = A + (size_t)gm * DIMd + gk;
        }
        const float4 av = *reinterpret_cast<const float4*>(ap);
        As[lk + 0][lr] = av.x; As[lk + 1][lr] = av.y;
        As[lk + 2][lr] = av.z; As[lk + 3][lr] = av.w;

        const float4 wv = *reinterpret_cast<const float4*>(
            W + (size_t)(n0 + lr) * DIMd + gk);
        Bs[lk + 0][lr] = wv.x; Bs[lk + 1][lr] = wv.y;
        Bs[lk + 2][lr] = wv.z; Bs[lk + 3][lr] = wv.w;
        __syncthreads();

#pragma unroll
        for (int k = 0; k < 8; k++) {
            float4 a0 = *reinterpret_cast<const float4*>(&As[k][ty * 8]);
            float4 a1 = *reinterpret_cast<const float4*>(&As[k][ty * 8 + 4]);
            float4 b0 = *reinterpret_cast<const float4*>(&Bs[k][tx * 8]);
            float4 b1 = *reinterpret_cast<const float4*>(&Bs[k][tx * 8 + 4]);
            float ar[8] = {a0.x, a0.y, a0.z, a0.w, a1.x, a1.y, a1.z, a1.w};
            float br[8] = {b0.x, b0.y, b0.z, b0.w, b1.x, b1.y, b1.z, b1.w};
#pragma unroll
            for (int i = 0; i < 8; i++)
#pragma unroll
                for (int j = 0; j < 8; j++) acc[i][j] += ar[i] * br[j];
        }
        __syncthreads();
    }

#pragma unroll
    for (int i = 0; i < 8; i++) {
        const int m = m0 + ty * 8 + i;
        const int b = m >> 11, tok = m & (Nn - 1);
#pragma unroll
        for (int j = 0; j < 8; j += 4) {
            const int n = n0 + tx * 8 + j;
            float4 o;
            o.x = acc[i][j + 0] + bias[n + 0];
            o.y = acc[i][j + 1] + bias[n + 1];
            o.z = acc[i][j + 2] + bias[n + 2];
            o.w = acc[i][j + 3] + bias[n + 3];
            if (SPLIT_OUT) {
                const int h = n >> 6, c = n & 63;
                *reinterpret_cast<float4*>(
                    C + ((size_t)((b * Hh + h) * Nn + tok)) * HDc + c) = o;
            } else {
                *reinterpret_cast<float4*>(C + (size_t)m * DIMd + n) = o;
            }
        }
    }
}

// ---------------------------------------------------------------------------
// Causal flash attention, fp32.
// Grid: (N/64 q-tiles, B*H). 256 threads. Online softmax, 4x4 reg tiles.
// ---------------------------------------------------------------------------
#define PAD 68

__global__ __launch_bounds__(256) void attn_kernel(
    const float* __restrict__ Qg, const float* __restrict__ Kg,
    const float* __restrict__ Vg, float* __restrict__ Og)
{
    extern __shared__ float sm[];
    float* Qs   = sm;                 // [64][PAD]  Qs[r][c]
    float* KsT  = Qs  + 64 * PAD;     // [64][PAD]  KsT[c][j] (transposed)
    float* Vs   = KsT + 64 * PAD;     // [64][PAD]  Vs[j][c]
    float* Ss   = Vs  + 64 * PAD;     // [64][PAD]  scores / probs
    float* rowM = Ss  + 64 * PAD;     // [64]
    float* rowL = rowM + 64;          // [64]
    float* rowF = rowL + 64;          // [64] rescale factors

    const int bh = blockIdx.y;
    const int qt = blockIdx.x;
    const int q0 = qt * 64;
    const size_t base = (size_t)bh * Nn * HDc;
    const float* Qb = Qg + base;
    const float* Kb = Kg + base;
    const float* Vb = Vg + base;

    const int tid = threadIdx.x;
    const int tx = tid & 15;   // S cols / O cols
    const int ty = tid >> 4;   // rows

    // Load Q tile (64x64)
    for (int i = tid; i < 64 * 16; i += 256) {
        const int r = i >> 4, c = (i & 15) << 2;
        *reinterpret_cast<float4*>(Qs + r * PAD + c) =
            *reinterpret_cast<const float4*>(Qb + (size_t)(q0 + r) * HDc + c);
    }
    if (tid < 64) { rowM[tid] = -1e30f; rowL[tid] = 0.f; }

    float o[4][4];
#pragma unroll
    for (int i = 0; i < 4; i++)
#pragma unroll
        for (int j = 0; j < 4; j++) o[i][j] = 0.f;
    __syncthreads();

    for (int kt = 0; kt <= qt; ++kt) {
        const int k0 = kt * 64;

        // Load K (transposed) and V tiles
        for (int i = tid; i < 64 * 16; i += 256) {
            const int r = i >> 4, c = (i & 15) << 2;
            const float4 kv = *reinterpret_cast<const float4*>(
                Kb + (size_t)(k0 + r) * HDc + c);
            KsT[(c + 0) * PAD + r] = kv.x;
            KsT[(c + 1) * PAD + r] = kv.y;
            KsT[(c + 2) * PAD + r] = kv.z;
            KsT[(c + 3) * PAD + r] = kv.w;
            *reinterpret_cast<float4*>(Vs + r * PAD + c) =
                *reinterpret_cast<const float4*>(Vb + (size_t)(k0 + r) * HDc + c);
        }
        __syncthreads();

        // S = Q K^T (4x4 per thread)
        float s[4][4];
#pragma unroll
        for (int i = 0; i < 4; i++)
#pragma unroll
            for (int j = 0; j < 4; j++) s[i][j] = 0.f;

#pragma unroll
        for (int c = 0; c < 64; c += 4) {
            float4 a[4];
#pragma unroll
            for (int i = 0; i < 4; i++)
                a[i] = *reinterpret_cast<const float4*>(
                    Qs + (ty * 4 + i) * PAD + c);
#pragma unroll
            for (int u = 0; u < 4; u++) {
                const float4 bu = *reinterpret_cast<const float4*>(
                    KsT + (c + u) * PAD + tx * 4);
#pragma unroll
                for (int i = 0; i < 4; i++) {
                    const float av = f4c(a[i], u);
                    s[i][0] += av * bu.x;
                    s[i][1] += av * bu.y;
                    s[i][2] += av * bu.z;
                    s[i][3] += av * bu.w;
                }
            }
        }

        // Scale, causal mask (diagonal tile only), store to smem
        const bool diag = (kt == qt);
#pragma unroll
        for (int i = 0; i < 4; i++) {
            const int r = ty * 4 + i;
            const int qrow = q0 + r;
#pragma unroll
            for (int j = 0; j < 4; j++) {
                float v = s[i][j] * ATTN_SCALE;
                if (diag && (k0 + tx * 4 + j) > qrow) v = -1e30f;
                Ss[r * PAD + tx * 4 + j] = v;
            }
        }
        __syncthreads();

        // Online softmax: 4 threads per row, 16 cols each
        {
            const int r = tid >> 2, p = tid & 3;
            float* srow = Ss + r * PAD + p * 16;
            float mx = -1e30f;
#pragma unroll
            for (int t = 0; t < 16; t++) mx = fmaxf(mx, srow[t]);
            mx = fmaxf(mx, __shfl_xor_sync(0xffffffffu, mx, 1));
            mx = fmaxf(mx, __shfl_xor_sync(0xffffffffu, mx, 2));
            const float m_old = rowM[r];
            const float m_new = fmaxf(m_old, mx);
            float sum = 0.f;
#pragma unroll
            for (int t = 0; t < 16; t++) {
                const float e = __expf(srow[t] - m_new);
                srow[t] = e;
                sum += e;
            }
            sum += __shfl_xor_sync(0xffffffffu, sum, 1);
            sum += __shfl_xor_sync(0xffffffffu, sum, 2);
            if (p == 0) {
                const float f = __expf(m_old - m_new);
                rowF[r] = f;
                rowM[r] = m_new;
                rowL[r] = rowL[r] * f + sum;
            }
        }
        __syncthreads();

        // Rescale O, accumulate O += P * V
#pragma unroll
        for (int i = 0; i < 4; i++) {
            const float f = rowF[ty * 4 + i];
#pragma unroll
            for (int j = 0; j < 4; j++) o[i][j] *= f;
        }
#pragma unroll
        for (int jj = 0; jj < 64; jj += 4) {
            float4 p[4];
#pragma unroll
            for (int i = 0; i < 4; i++)
                p[i] = *reinterpret_cast<const float4*>(
                    Ss + (ty * 4 + i) * PAD + jj);
#pragma unroll
            for (int u = 0; u < 4; u++) {
                const float4 vv = *reinterpret_cast<const float4*>(
                    Vs + (jj + u) * PAD + tx * 4);
#pragma unroll
                for (int i = 0; i < 4; i++) {
                    const float pv = f4c(p[i], u);
                    o[i][0] += pv * vv.x;
                    o[i][1] += pv * vv.y;
                    o[i][2] += pv * vv.z;
                    o[i][3] += pv * vv.w;
                }
            }
        }
        __syncthreads();
    }

    // Finalize: divide by row sum, write out
#pragma unroll
    for (int i = 0; i < 4; i++) {
        const int r = ty * 4 + i;
        const float inv = 1.f / rowL[r];
        float4 ov;
        ov.x = o[i][0] * inv;
        ov.y = o[i][1] * inv;
        ov.z = o[i][2] * inv;
        ov.w = o[i][3] * inv;
        *reinterpret_cast<float4*>(
            Og + base + (size_t)(q0 + r) * HDc + tx * 4) = ov;
    }
}

// ---------------------------------------------------------------------------
extern "C" void kernel_launch(void* const* d_in, const int* in_sizes, int n_in,
                              void* d_out, int out_size)
{
    const float* q  = (const float*)d_in[0];
    const float* k  = (const float*)d_in[1];
    const float* v  = (const float*)d_in[2];
    // d_in[3] = mask (guaranteed tril; causality applied analytically)
    const float* Wq = (const float*)d_in[4];
    const float* bq = (const float*)d_in[5];
    const float* Wk = (const float*)d_in[6];
    const float* bk = (const float*)d_in[7];
    const float* Wv = (const float*)d_in[8];
    const float* bv = (const float*)d_in[9];
    const float* Wo = (const float*)d_in[10];
    const float* bo = (const float*)d_in[11];
    float* out = (float*)d_out;

    float *qh, *kh, *vh, *ao;
    cudaGetSymbolAddress((void**)&qh, g_qh);
    cudaGetSymbolAddress((void**)&kh, g_kh);
    cudaGetSymbolAddress((void**)&vh, g_vh);
    cudaGetSymbolAddress((void**)&ao, g_ao);

    const dim3 pg(DIMd / 128, Mrows / 128);
    proj_gemm<false, true><<<pg, 256>>>(q, Wq, bq, qh);
    proj_gemm<false, true><<<pg, 256>>>(k, Wk, bk, kh);
    proj_gemm<false, true><<<pg, 256>>>(v, Wv, bv, vh);

    const int smem_bytes = (4 * 64 * PAD + 3 * 64) * (int)sizeof(float); // 70400
    cudaFuncSetAttribute(attn_kernel,
                         cudaFuncAttributeMaxDynamicSharedMemorySize, smem_bytes);
    attn_kernel<<<dim3(Nn / 64, Bb * Hh), 256, smem_bytes>>>(qh, kh, vh, ao);

    proj_gemm<true, false><<<pg, 256>>>(ao, Wo, bo, out);
}

// round 2
// speedup vs baseline: 2.6231x; 2.6231x over previous
#include <cuda_runtime.h>
#include <math.h>
#include <stdint.h>

constexpr int Bb   = 2;
constexpr int Hh   = 16;
constexpr int Nn   = 2048;
constexpr int HDc  = 64;
constexpr int DIMd = 1024;
constexpr int Mrows = Bb * Nn;       // 4096
constexpr float ATTN_SCALE = 0.125f;

// Scratch [B,H,N,HD]
__device__ float g_qh[Bb * Hh * Nn * HDc];
__device__ float g_kh[Bb * Hh * Nn * HDc];
__device__ float g_vh[Bb * Hh * Nn * HDc];
__device__ float g_ao[Bb * Hh * Nn * HDc];

__device__ __forceinline__ uint32_t tf32r(float x) {
    uint32_t y;
    asm("cvt.rna.tf32.f32 %0, %1;" : "=r"(y) : "f"(x));
    return y;
}

__device__ __forceinline__ void mma8(float* d, const uint32_t* a, const uint32_t* b) {
    asm volatile(
        "mma.sync.aligned.m16n8k8.row.col.f32.tf32.tf32.f32 "
        "{%0,%1,%2,%3}, {%4,%5,%6,%7}, {%8,%9}, {%0,%1,%2,%3};\n"
        : "+f"(d[0]), "+f"(d[1]), "+f"(d[2]), "+f"(d[3])
        : "r"(a[0]), "r"(a[1]), "r"(a[2]), "r"(a[3]), "r"(b[0]), "r"(b[1]));
}

// ---------------------------------------------------------------------------
// Projection GEMM (tf32 tensor cores): C[m,n] = sum_k A[m,k]*W[n,k] + bias[n]
// 128x128x32 tile, 256 threads (8 warps, 2x4), 64x32 per warp (4x4 mma tiles)
// ---------------------------------------------------------------------------
constexpr int SKA = 36;  // smem k-stride (bank = (4*gid+tig)%32, conflict-free)

template <bool SPLIT_IN>
__device__ __forceinline__ void ld_tileA(float4* r, const float* __restrict__ A,
                                         int m0, int k0, int tid) {
#pragma unroll
    for (int i = 0; i < 4; i++) {
        const int idx = tid + i * 256;
        const int row = idx >> 3, q = (idx & 7) << 2;
        const int gm = m0 + row, gk = k0 + q;
        const float* ap;
        if (SPLIT_IN) {
            const int b = gm >> 11, tok = gm & (Nn - 1);
            const int h = gk >> 6, cc = gk & 63;
            ap = A + ((size_t)((b * Hh + h) * Nn + tok)) * HDc + cc;
        } else {
            ap = A + (size_t)gm * DIMd + gk;
        }
        r[i] = *reinterpret_cast<const float4*>(ap);
    }
}

__device__ __forceinline__ void ld_tileW(float4* r, const float* __restrict__ W,
                                         int n0, int k0, int tid) {
#pragma unroll
    for (int i = 0; i < 4; i++) {
        const int idx = tid + i * 256;
        const int row = idx >> 3, q = (idx & 7) << 2;
        r[i] = *reinterpret_cast<const float4*>(W + (size_t)(n0 + row) * DIMd + k0 + q);
    }
}

__device__ __forceinline__ void st_tile(uint32_t* S, const float4* r, int tid) {
#pragma unroll
    for (int i = 0; i < 4; i++) {
        const int idx = tid + i * 256;
        const int row = idx >> 3, q = (idx & 7) << 2;
        uint32_t* p = S + row * SKA + q;
        p[0] = tf32r(r[i].x); p[1] = tf32r(r[i].y);
        p[2] = tf32r(r[i].z); p[3] = tf32r(r[i].w);
    }
}

template <bool SPLIT_IN, bool SPLIT_OUT>
__global__ __launch_bounds__(256) void proj_tc(
    const float* __restrict__ A, const float* __restrict__ W,
    const float* __restrict__ bias, float* __restrict__ C)
{
    __shared__ uint32_t As[128 * SKA];
    __shared__ uint32_t Ws[128 * SKA];

    const int m0 = blockIdx.y * 128, n0 = blockIdx.x * 128;
    const int tid = threadIdx.x;
    const int w = tid >> 5, lane = tid & 31;
    const int gid = lane >> 2, tig = lane & 3;
    const int mbase = (w & 1) * 64;
    const int nbase = (w >> 1) * 32;

    float c[4][4][4];
#pragma unroll
    for (int mi = 0; mi < 4; mi++)
#pragma unroll
        for (int ni = 0; ni < 4; ni++)
#pragma unroll
            for (int u = 0; u < 4; u++) c[mi][ni][u] = 0.f;

    float4 ra[4], rw[4];
    ld_tileA<SPLIT_IN>(ra, A, m0, 0, tid);
    ld_tileW(rw, W, n0, 0, tid);
    st_tile(As, ra, tid);
    st_tile(Ws, rw, tid);
    __syncthreads();

    constexpr int ITERS = DIMd / 32;
    for (int kt = 0; kt < ITERS; kt++) {
        if (kt + 1 < ITERS) {
            ld_tileA<SPLIT_IN>(ra, A, m0, (kt + 1) * 32, tid);
            ld_tileW(rw, W, n0, (kt + 1) * 32, tid);
        }
#pragma unroll
        for (int kk = 0; kk < 32; kk += 8) {
            uint32_t af[4][4];
#pragma unroll
            for (int mi = 0; mi < 4; mi++) {
                const uint32_t* p = As + (mbase + mi * 16 + gid) * SKA + kk + tig;
                af[mi][0] = p[0];
                af[mi][1] = p[8 * SKA];
                af[mi][2] = p[4];
                af[mi][3] = p[8 * SKA + 4];
            }
            uint32_t bf[4][2];
#pragma unroll
            for (int ni = 0; ni < 4; ni++) {
                const uint32_t* p = Ws + (nbase + ni * 8 + gid) * SKA + kk + tig;
                bf[ni][0] = p[0];
                bf[ni][1] = p[4];
            }
#pragma unroll
            for (int mi = 0; mi < 4; mi++)
#pragma unroll
                for (int ni = 0; ni < 4; ni++)
                    mma8(c[mi][ni], af[mi], bf[ni]);
        }
        __syncthreads();
        if (kt + 1 < ITERS) {
            st_tile(As, ra, tid);
            st_tile(Ws, rw, tid);
            __syncthreads();
        }
    }

    // Epilogue
#pragma unroll
    for (int mi = 0; mi < 4; mi++) {
#pragma unroll
        for (int ni = 0; ni < 4; ni++) {
            const int n = n0 + nbase + ni * 8 + 2 * tig;
            const float bx = bias[n], by = bias[n + 1];
#pragma unroll
            for (int hr = 0; hr < 2; hr++) {
                const int m = m0 + mbase + mi * 16 + gid + hr * 8;
                float2 o;
                o.x = c[mi][ni][hr * 2 + 0] + bx;
                o.y = c[mi][ni][hr * 2 + 1] + by;
                if (SPLIT_OUT) {
                    const int b = m >> 11, tok = m & (Nn - 1);
                    const int h = n >> 6, cc = n & 63;
                    *reinterpret_cast<float2*>(
                        C + ((size_t)((b * Hh + h) * Nn + tok)) * HDc + cc) = o;
                } else {
                    *reinterpret_cast<float2*>(C + (size_t)m * DIMd + n) = o;
                }
            }
        }
    }
}

// ---------------------------------------------------------------------------
// Causal flash attention with tf32 mma. 64 q-rows/CTA, 256 threads (8 warps,
// 4x2 layout: each warp 16x32 of the 64x64 S / O tiles). Q in register frags.
// ---------------------------------------------------------------------------
#define APAD 68

__global__ __launch_bounds__(256) void attn_tc(
    const float* __restrict__ Qg, const float* __restrict__ Kg,
    const float* __restrict__ Vg, float* __restrict__ Og)
{
    extern __shared__ float sm[];
    float* Ks   = sm;                 // [64][APAD] key-token major (tf32 bits)
    float* Vs   = Ks + 64 * APAD;     // [64][APAD] (tf32 bits)
    float* Ss   = Vs + 64 * APAD;     // [64][APAD] scores / probs
    float* rowM = Ss + 64 * APAD;
    float* rowL = rowM + 64;
    float* rowF = rowL + 64;

    const int bh = blockIdx.y;
    const int qt = blockIdx.x;
    const int q0 = qt * 64;
    const size_t base = (size_t)bh * Nn * HDc;

    const int tid = threadIdx.x;
    const int w = tid >> 5, lane = tid & 31;
    const int gid = lane >> 2, tig = lane & 3;
    const int mrow = (w & 3) * 16;   // S/O row base within 64
    const int ncol = (w >> 2) * 32;  // S col / O col base within 64

    // Q fragments (8 k-steps of 8)
    uint32_t qf[8][4];
    {
        const float* Qb  = Qg + base + (size_t)(q0 + mrow + gid) * HDc;
        const float* Qb8 = Qb + 8 * HDc;
#pragma unroll
        for (int s = 0; s < 8; s++) {
            const int kc = s * 8 + tig;
            qf[s][0] = tf32r(Qb[kc]);
            qf[s][1] = tf32r(Qb8[kc]);
            qf[s][2] = tf32r(Qb[kc + 4]);
            qf[s][3] = tf32r(Qb8[kc + 4]);
        }
    }
    if (tid < 64) { rowM[tid] = -1e30f; rowL[tid] = 0.f; }

    float o[4][4];
#pragma unroll
    for (int ni = 0; ni < 4; ni++)
#pragma unroll
        for (int u = 0; u < 4; u++) o[ni][u] = 0.f;
    __syncthreads();

    for (int kt = 0; kt <= qt; ++kt) {
        const int k0 = kt * 64;

        // Load K,V tiles (converted to tf32 bit patterns)
        for (int i = tid; i < 64 * 16; i += 256) {
            const int r = i >> 4, cq = (i & 15) << 2;
            const float4 kv = *reinterpret_cast<const float4*>(
                Kg + base + (size_t)(k0 + r) * HDc + cq);
            uint32_t* kp = reinterpret_cast<uint32_t*>(Ks) + r * APAD + cq;
            kp[0] = tf32r(kv.x); kp[1] = tf32r(kv.y);
            kp[2] = tf32r(kv.z); kp[3] = tf32r(kv.w);
            const float4 vv = *reinterpret_cast<const float4*>(
                Vg + base + (size_t)(k0 + r) * HDc + cq);
            uint32_t* vp = reinterpret_cast<uint32_t*>(Vs) + r * APAD + cq;
            vp[0] = tf32r(vv.x); vp[1] = tf32r(vv.y);
            vp[2] = tf32r(vv.z); vp[3] = tf32r(vv.w);
        }
        __syncthreads();

        // S = Q K^T
        float s4[4][4];
#pragma unroll
        for (int ni = 0; ni < 4; ni++)
#pragma unroll
            for (int u = 0; u < 4; u++) s4[ni][u] = 0.f;

#pragma unroll
        for (int s = 0; s < 8; s++) {
            const int kk = s * 8;
            uint32_t bf[4][2];
#pragma unroll
            for (int ni = 0; ni < 4; ni++) {
                const uint32_t* p = reinterpret_cast<const uint32_t*>(Ks) +
                                    (ncol + ni * 8 + gid) * APAD + kk + tig;
                bf[ni][0] = p[0];
                bf[ni][1] = p[4];
            }
#pragma unroll
            for (int ni = 0; ni < 4; ni++)
                mma8(s4[ni], qf[s], bf[ni]);
        }

        // Scale + causal mask (diag tile only) + write S to smem
        const bool diag = (kt == qt);
#pragma unroll
        for (int ni = 0; ni < 4; ni++) {
            const int cc = ncol + ni * 8 + 2 * tig;
#pragma unroll
            for (int hr = 0; hr < 2; hr++) {
                const int r = mrow + gid + hr * 8;
                float vx = s4[ni][hr * 2 + 0] * ATTN_SCALE;
                float vy = s4[ni][hr * 2 + 1] * ATTN_SCALE;
                if (diag) {
                    const int qrow = q0 + r;
                    if (k0 + cc > qrow)     vx = -1e30f;
                    if (k0 + cc + 1 > qrow) vy = -1e30f;
                }
                float2 sv; sv.x = vx; sv.y = vy;
                *reinterpret_cast<float2*>(Ss + r * APAD + cc) = sv;
            }
        }
        __syncthreads();

        // Online softmax: 4 threads per row, 16 cols each; probs tf32-rounded
        {
            const int r = tid >> 2, p = tid & 3;
            float* srow = Ss + r * APAD + p * 16;
            float mx = -1e30f;
#pragma unroll
            for (int t = 0; t < 16; t++) mx = fmaxf(mx, srow[t]);
            mx = fmaxf(mx, __shfl_xor_sync(0xffffffffu, mx, 1));
            mx = fmaxf(mx, __shfl_xor_sync(0xffffffffu, mx, 2));
            const float m_old = rowM[r];
            const float m_new = fmaxf(m_old, mx);
            float sum = 0.f;
#pragma unroll
            for (int t = 0; t < 16; t++) {
                const float e = __expf(srow[t] - m_new);
                const float er = __uint_as_float(tf32r(e));
                srow[t] = er;
                sum += er;
            }
            sum += __shfl_xor_sync(0xffffffffu, sum, 1);
            sum += __shfl_xor_sync(0xffffffffu, sum, 2);
            if (p == 0) {
                const float f = __expf(m_old - m_new);
                rowF[r] = f;
                rowM[r] = m_new;
                rowL[r] = rowL[r] * f + sum;
            }
        }
        __syncthreads();

        // Rescale O accumulators
        {
            const float f0 = rowF[mrow + gid];
            const float f1 = rowF[mrow + gid + 8];
#pragma unroll
            for (int ni = 0; ni < 4; ni++) {
                o[ni][0] *= f0; o[ni][1] *= f0;
                o[ni][2] *= f1; o[ni][3] *= f1;
            }
        }

        // O += P * V
#pragma unroll
        for (int s = 0; s < 8; s++) {
            const int kk = s * 8;
            uint32_t af[4];
            const uint32_t* p = reinterpret_cast<const uint32_t*>(Ss) +
                                (mrow + gid) * APAD + kk + tig;
            af[0] = p[0];
            af[1] = p[8 * APAD];
            af[2] = p[4];
            af[3] = p[8 * APAD + 4];
            uint32_t bf[4][2];
#pragma unroll
            for (int ni = 0; ni < 4; ni++) {
                const uint32_t* q = reinterpret_cast<const uint32_t*>(Vs) +
                                    (kk + tig) * APAD + ncol + ni * 8 + gid;
                bf[ni][0] = q[0];
                bf[ni][1] = q[4 * APAD];
            }
#pragma unroll
            for (int ni = 0; ni < 4; ni++)
                mma8(o[ni], af, bf[ni]);
        }
        __syncthreads();
    }

    // Finalize
    {
        const float inv0 = 1.f / rowL[mrow + gid];
        const float inv1 = 1.f / rowL[mrow + gid + 8];
        const int r0 = q0 + mrow + gid;
#pragma unroll
        for (int ni = 0; ni < 4; ni++) {
            const int cc = ncol + ni * 8 + 2 * tig;
            float2 o0, o1;
            o0.x = o[ni][0] * inv0; o0.y = o[ni][1] * inv0;
            o1.x = o[ni][2] * inv1; o1.y = o[ni][3] * inv1;
            *reinterpret_cast<float2*>(Og + base + (size_t)r0 * HDc + cc) = o0;
            *reinterpret_cast<float2*>(Og + base + (size_t)(r0 + 8) * HDc + cc) = o1;
        }
    }
}

// ---------------------------------------------------------------------------
extern "C" void kernel_launch(void* const* d_in, const int* in_sizes, int n_in,
                              void* d_out, int out_size)
{
    const float* q  = (const float*)d_in[0];
    const float* k  = (const float*)d_in[1];
    const float* v  = (const float*)d_in[2];
    // d_in[3] = mask (tril; causality applied analytically)
    const float* Wq = (const float*)d_in[4];
    const float* bq = (const float*)d_in[5];
    const float* Wk = (const float*)d_in[6];
    const float* bk = (const float*)d_in[7];
    const float* Wv = (const float*)d_in[8];
    const float* bv = (const float*)d_in[9];
    const float* Wo = (const float*)d_in[10];
    const float* bo = (const float*)d_in[11];
    float* out = (float*)d_out;

    float *qh, *kh, *vh, *ao;
    cudaGetSymbolAddress((void**)&qh, g_qh);
    cudaGetSymbolAddress((void**)&kh, g_kh);
    cudaGetSymbolAddress((void**)&vh, g_vh);
    cudaGetSymbolAddress((void**)&ao, g_ao);

    const dim3 pg(DIMd / 128, Mrows / 128);
    proj_tc<false, true><<<pg, 256>>>(q, Wq, bq, qh);
    proj_tc<false, true><<<pg, 256>>>(k, Wk, bk, kh);
    proj_tc<false, true><<<pg, 256>>>(v, Wv, bv, vh);

    const int smem_bytes = (3 * 64 * APAD + 3 * 64) * (int)sizeof(float); // ~53KB
    static int attn_cfg = 0;
    if (!attn_cfg) {
        cudaFuncSetAttribute(attn_tc,
                             cudaFuncAttributeMaxDynamicSharedMemorySize, smem_bytes);
        attn_cfg = 1;
    }
    attn_tc<<<dim3(Nn / 64, Bb * Hh), 256, smem_bytes>>>(qh, kh, vh, ao);

    proj_tc<true, false><<<pg, 256>>>(ao, Wo, bo, out);
}

// round 3
// speedup vs baseline: 2.8583x; 1.0897x over previous
#include <cuda_runtime.h>
#include <math.h>
#include <stdint.h>

constexpr int Bb   = 2;
constexpr int Hh   = 16;
constexpr int Nn   = 2048;
constexpr int HDc  = 64;
constexpr int DIMd = 1024;
constexpr int Mrows = Bb * Nn;       // 4096
constexpr float ATTN_SCALE = 0.125f;

// Scratch buffers
__device__ float g_qh[Bb * Hh * Nn * HDc];   // Q heads (tf32 bits, pre-scaled)
__device__ float g_kh[Bb * Hh * Nn * HDc];   // K heads (tf32 bits)
__device__ float g_vh[Bb * Hh * Nn * HDc];   // V heads (tf32 bits)
__device__ float g_ao[Bb * Hh * Nn * HDc];   // attn out (tf32 bits)
__device__ float g_qt[Mrows * DIMd];         // tf32 copies of inputs
__device__ float g_kt[Mrows * DIMd];
__device__ float g_vt[Mrows * DIMd];
__device__ float g_wq[DIMd * DIMd];          // tf32 copies of weights
__device__ float g_wk[DIMd * DIMd];
__device__ float g_wv[DIMd * DIMd];
__device__ float g_wo[DIMd * DIMd];

__device__ __forceinline__ uint32_t tf32r(float x) {
    uint32_t y;
    asm("cvt.rna.tf32.f32 %0, %1;" : "=r"(y) : "f"(x));
    return y;
}

__device__ __forceinline__ void mma8(float* d, const uint32_t* a, const uint32_t* b) {
    asm volatile(
        "mma.sync.aligned.m16n8k8.row.col.f32.tf32.tf32.f32 "
        "{%0,%1,%2,%3}, {%4,%5,%6,%7}, {%8,%9}, {%0,%1,%2,%3};\n"
        : "+f"(d[0]), "+f"(d[1]), "+f"(d[2]), "+f"(d[3])
        : "r"(a[0]), "r"(a[1]), "r"(a[2]), "r"(a[3]), "r"(b[0]), "r"(b[1]));
}

__device__ __forceinline__ void cp16(uint32_t daddr, const void* src) {
    asm volatile("cp.async.cg.shared.global [%0], [%1], 16;\n"
                 :: "r"(daddr), "l"(src));
}
__device__ __forceinline__ void cp_commit() {
    asm volatile("cp.async.commit_group;\n");
}
template <int N>
__device__ __forceinline__ void cp_wait() {
    asm volatile("cp.async.wait_group %0;\n" :: "n"(N));
}

// ---------------------------------------------------------------------------
// Elementwise tf32 (RNA) pre-conversion
// ---------------------------------------------------------------------------
__global__ __launch_bounds__(256) void cvt_tf32(const float4* __restrict__ s,
                                                float4* __restrict__ d, int n4) {
    int i = blockIdx.x * 256 + threadIdx.x;
    if (i < n4) {
        float4 v = s[i];
        float4 o;
        o.x = __uint_as_float(tf32r(v.x));
        o.y = __uint_as_float(tf32r(v.y));
        o.z = __uint_as_float(tf32r(v.z));
        o.w = __uint_as_float(tf32r(v.w));
        d[i] = o;
    }
}

// ---------------------------------------------------------------------------
// Projection GEMM body: C[m,n] = (sum_k A[m,k]*W[n,k] + bias[n]) * scale
// A, W already tf32-rounded in gmem. 128x128x32 tiles, cp.async double buffer.
// 256 threads, 8 warps (2x4), 64x32 per warp, 4x4 m16n8k8 tiles.
// ---------------------------------------------------------------------------
constexpr int SKA = 36;                 // smem k-stride words (conflict-free)
constexpr int PROJ_SMEM = 4 * 128 * SKA * 4;  // 73728 B

template <bool SPLIT_IN, bool SPLIT_OUT, bool ROUND>
__device__ __forceinline__ void proj_body(
    const float* __restrict__ A, const float* __restrict__ W,
    const float* __restrict__ bias, float* __restrict__ C, float scale,
    float* smf)
{
    const int m0 = blockIdx.y * 128, n0 = blockIdx.x * 128;
    const int tid = threadIdx.x;
    const int w = tid >> 5, lane = tid & 31;
    const int gid = lane >> 2, tig = lane & 3;
    const int mbase = (w & 1) * 64;
    const int nbase = (w >> 1) * 32;

    const uint32_t* Asb[2] = {(const uint32_t*)smf,
                              (const uint32_t*)smf + 128 * SKA};
    const uint32_t* Wsb[2] = {(const uint32_t*)smf + 2 * 128 * SKA,
                              (const uint32_t*)smf + 3 * 128 * SKA};
    const uint32_t su = (uint32_t)__cvta_generic_to_shared(smf);
    const uint32_t asu[2] = {su, su + 128 * SKA * 4};
    const uint32_t wsu[2] = {su + 2 * 128 * SKA * 4, su + 3 * 128 * SKA * 4};

    auto load_tiles = [&](int kt, int buf) {
        const int k0 = kt * 32;
#pragma unroll
        for (int t = 0; t < 4; t++) {
            const int idx = tid + t * 256;
            const int r = idx >> 3, c = (idx & 7) << 2;
            const float* ap;
            if (SPLIT_IN) {
                const int gm = m0 + r, gk = k0 + c;
                const int b = gm >> 11, tok = gm & (Nn - 1);
                const int h = gk >> 6, cc = gk & 63;
                ap = A + ((size_t)((b * Hh + h) * Nn + tok)) * HDc + cc;
            } else {
                ap = A + (size_t)(m0 + r) * DIMd + k0 + c;
            }
            cp16(asu[buf] + (r * SKA + c) * 4, ap);
            cp16(wsu[buf] + (r * SKA + c) * 4,
                 W + (size_t)(n0 + r) * DIMd + k0 + c);
        }
        cp_commit();
    };

    float c[4][4][4];
#pragma unroll
    for (int mi = 0; mi < 4; mi++)
#pragma unroll
        for (int ni = 0; ni < 4; ni++)
#pragma unroll
            for (int u = 0; u < 4; u++) c[mi][ni][u] = 0.f;

    load_tiles(0, 0);
    for (int kt = 0; kt < 32; kt++) {
        const int cur = kt & 1;
        if (kt < 31) { load_tiles(kt + 1, cur ^ 1); cp_wait<1>(); }
        else         { cp_wait<0>(); }
        __syncthreads();

        const uint32_t* Ab = Asb[cur];
        const uint32_t* Wb = Wsb[cur];
#pragma unroll
        for (int kk = 0; kk < 32; kk += 8) {
            uint32_t af[4][4];
#pragma unroll
            for (int mi = 0; mi < 4; mi++) {
                const uint32_t* p = Ab + (mbase + mi * 16 + gid) * SKA + kk + tig;
                af[mi][0] = p[0];
                af[mi][1] = p[8 * SKA];
                af[mi][2] = p[4];
                af[mi][3] = p[8 * SKA + 4];
            }
            uint32_t bf[4][2];
#pragma unroll
            for (int ni = 0; ni < 4; ni++) {
                const uint32_t* p = Wb + (nbase + ni * 8 + gid) * SKA + kk + tig;
                bf[ni][0] = p[0];
                bf[ni][1] = p[4];
            }
#pragma unroll
            for (int mi = 0; mi < 4; mi++)
#pragma unroll
                for (int ni = 0; ni < 4; ni++)
                    mma8(c[mi][ni], af[mi], bf[ni]);
        }
        __syncthreads();
    }

    // Epilogue
#pragma unroll
    for (int mi = 0; mi < 4; mi++) {
#pragma unroll
        for (int ni = 0; ni < 4; ni++) {
            const int n = n0 + nbase + ni * 8 + 2 * tig;
            const float bx = bias[n], by = bias[n + 1];
#pragma unroll
            for (int hr = 0; hr < 2; hr++) {
                const int m = m0 + mbase + mi * 16 + gid + hr * 8;
                float2 o;
                o.x = (c[mi][ni][hr * 2 + 0] + bx) * scale;
                o.y = (c[mi][ni][hr * 2 + 1] + by) * scale;
                if (ROUND) {
                    o.x = __uint_as_float(tf32r(o.x));
                    o.y = __uint_as_float(tf32r(o.y));
                }
                if (SPLIT_OUT) {
                    const int b = m >> 11, tok = m & (Nn - 1);
                    const int h = n >> 6, cc = n & 63;
                    *reinterpret_cast<float2*>(
                        C + ((size_t)((b * Hh + h) * Nn + tok)) * HDc + cc) = o;
                } else {
                    *reinterpret_cast<float2*>(C + (size_t)m * DIMd + n) = o;
                }
            }
        }
    }
}

__global__ __launch_bounds__(256) void qkv_proj(
    const float* aq, const float* ak, const float* av,
    const float* wq, const float* wk, const float* wv,
    const float* bq, const float* bk, const float* bv,
    float* cq, float* ck, float* cv)
{
    extern __shared__ float smf[];
    const int z = blockIdx.z;
    const float* A = (z == 0) ? aq : (z == 1) ? ak : av;
    const float* W = (z == 0) ? wq : (z == 1) ? wk : wv;
    const float* b = (z == 0) ? bq : (z == 1) ? bk : bv;
    float*       C = (z == 0) ? cq : (z == 1) ? ck : cv;
    const float scale = (z == 0) ? ATTN_SCALE : 1.0f;
    proj_body<false, true, true>(A, W, b, C, scale, smf);
}

__global__ __launch_bounds__(256) void o_proj(
    const float* A, const float* W, const float* b, float* C)
{
    extern __shared__ float smf[];
    proj_body<true, false, false>(A, W, b, C, 1.0f, smf);
}

// ---------------------------------------------------------------------------
// Causal flash attention: 64 q-rows/CTA, 4 warps, each warp owns a full
// 16x64 strip of S/O. Softmax entirely in registers (quad shfl reductions).
// K/V tiles cp.async double-buffered. Inputs are tf32 bits (Q pre-scaled).
// ---------------------------------------------------------------------------
constexpr int AST = 68;  // smem row stride (words)
constexpr int ATT_SMEM = 5 * 64 * AST * 4;  // 2xK, 2xV, P = 87040 B

__global__ __launch_bounds__(128) void attn2(
    const float* __restrict__ Qg, const float* __restrict__ Kg,
    const float* __restrict__ Vg, float* __restrict__ Og)
{
    extern __shared__ float smf[];
    const uint32_t su = (uint32_t)__cvta_generic_to_shared(smf);
    const uint32_t ksu[2] = {su, su + 64 * AST * 4};
    const uint32_t vsu[2] = {su + 2 * 64 * AST * 4, su + 3 * 64 * AST * 4};
    const uint32_t* Ksb[2] = {(const uint32_t*)smf,
                              (const uint32_t*)smf + 64 * AST};
    const uint32_t* Vsb[2] = {(const uint32_t*)smf + 2 * 64 * AST,
                              (const uint32_t*)smf + 3 * 64 * AST};
    uint32_t* Psu = (uint32_t*)smf + 4 * 64 * AST;

    const int bh = blockIdx.y;
    const int qt = blockIdx.x;
    const int q0 = qt * 64;
    const size_t base = (size_t)bh * Nn * HDc;

    const int tid = threadIdx.x;
    const int w = tid >> 5, lane = tid & 31;
    const int gid = lane >> 2, tig = lane & 3;
    const int mrow = w * 16;

    auto issueKV = [&](int t_kt, int buf) {
        const float* Kb = Kg + base + (size_t)(t_kt * 64) * HDc;
        const float* Vb = Vg + base + (size_t)(t_kt * 64) * HDc;
#pragma unroll
        for (int t = 0; t < 8; t++) {
            const int idx = tid + t * 128;
            const int r = idx >> 4, cc = (idx & 15) << 2;
            cp16(ksu[buf] + (r * AST + cc) * 4, Kb + r * HDc + cc);
            cp16(vsu[buf] + (r * AST + cc) * 4, Vb + r * HDc + cc);
        }
        cp_commit();
    };

    // Q fragments: warp rows mrow+gid, mrow+gid+8; all 64 hd cols
    uint32_t qf[8][4];
    {
        const uint32_t* Qu = (const uint32_t*)(Qg + base) +
                             (size_t)(q0 + mrow + gid) * HDc;
#pragma unroll
        for (int s = 0; s < 8; s++) {
            const int kc = s * 8 + tig;
            qf[s][0] = Qu[kc];
            qf[s][1] = Qu[8 * HDc + kc];
            qf[s][2] = Qu[kc + 4];
            qf[s][3] = Qu[8 * HDc + kc + 4];
        }
    }

    float o[8][4];
#pragma unroll
    for (int ni = 0; ni < 8; ni++)
#pragma unroll
        for (int u = 0; u < 4; u++) o[ni][u] = 0.f;
    float m0r = -1e30f, m1r = -1e30f, l0 = 0.f, l1 = 0.f;

    issueKV(0, 0);

    for (int kt = 0; kt <= qt; kt++) {
        const int cur = kt & 1;
        if (kt < qt) { issueKV(kt + 1, cur ^ 1); cp_wait<1>(); }
        else         { cp_wait<0>(); }
        __syncthreads();

        // ---- S = Q K^T (16x64 per warp) ----
        float s4[8][4];
#pragma unroll
        for (int ni = 0; ni < 8; ni++)
#pragma unroll
            for (int u = 0; u < 4; u++) s4[ni][u] = 0.f;

        const uint32_t* Kb = Ksb[cur];
#pragma unroll
        for (int s = 0; s < 8; s++) {
            const int kk = s * 8;
            uint32_t bf[8][2];
#pragma unroll
            for (int ni = 0; ni < 8; ni++) {
                const uint32_t* p = Kb + (ni * 8 + gid) * AST + kk + tig;
                bf[ni][0] = p[0];
                bf[ni][1] = p[4];
            }
#pragma unroll
            for (int ni = 0; ni < 8; ni++)
                mma8(s4[ni], qf[s], bf[ni]);
        }

        // ---- causal mask (diagonal tile only) ----
        if (kt == qt) {
            const int r0 = q0 + mrow + gid, r1 = r0 + 8;
            const int k0 = kt * 64;
#pragma unroll
            for (int ni = 0; ni < 8; ni++) {
                const int cc = k0 + ni * 8 + 2 * tig;
                if (cc > r0)     s4[ni][0] = -1e30f;
                if (cc + 1 > r0) s4[ni][1] = -1e30f;
                if (cc > r1)     s4[ni][2] = -1e30f;
                if (cc + 1 > r1) s4[ni][3] = -1e30f;
            }
        }

        // ---- register softmax (rows warp-local; quad reduction) ----
        float mx0 = -1e30f, mx1 = -1e30f;
#pragma unroll
        for (int ni = 0; ni < 8; ni++) {
            mx0 = fmaxf(mx0, fmaxf(s4[ni][0], s4[ni][1]));
            mx1 = fmaxf(mx1, fmaxf(s4[ni][2], s4[ni][3]));
        }
        mx0 = fmaxf(mx0, __shfl_xor_sync(0xffffffffu, mx0, 1));
        mx0 = fmaxf(mx0, __shfl_xor_sync(0xffffffffu, mx0, 2));
        mx1 = fmaxf(mx1, __shfl_xor_sync(0xffffffffu, mx1, 1));
        mx1 = fmaxf(mx1, __shfl_xor_sync(0xffffffffu, mx1, 2));
        const float mn0 = fmaxf(m0r, mx0);
        const float mn1 = fmaxf(m1r, mx1);
        const float f0 = __expf(m0r - mn0);
        const float f1 = __expf(m1r - mn1);
        m0r = mn0; m1r = mn1;

        float sum0 = 0.f, sum1 = 0.f;
        uint32_t* Pw = Psu + (mrow + gid) * AST + 2 * tig;
#pragma unroll
        for (int ni = 0; ni < 8; ni++) {
            const float e0 = __expf(s4[ni][0] - mn0);
            const float e1 = __expf(s4[ni][1] - mn0);
            const float e2 = __expf(s4[ni][2] - mn1);
            const float e3 = __expf(s4[ni][3] - mn1);
            sum0 += e0 + e1;
            sum1 += e2 + e3;
            uint2 pa, pb;
            pa.x = tf32r(e0); pa.y = tf32r(e1);
            pb.x = tf32r(e2); pb.y = tf32r(e3);
            *reinterpret_cast<uint2*>(Pw + ni * 8) = pa;
            *reinterpret_cast<uint2*>(Pw + 8 * AST + ni * 8) = pb;
        }
        sum0 += __shfl_xor_sync(0xffffffffu, sum0, 1);
        sum0 += __shfl_xor_sync(0xffffffffu, sum0, 2);
        sum1 += __shfl_xor_sync(0xffffffffu, sum1, 1);
        sum1 += __shfl_xor_sync(0xffffffffu, sum1, 2);
        l0 = l0 * f0 + sum0;
        l1 = l1 * f1 + sum1;

#pragma unroll
        for (int ni = 0; ni < 8; ni++) {
            o[ni][0] *= f0; o[ni][1] *= f0;
            o[ni][2] *= f1; o[ni][3] *= f1;
        }
        __syncwarp();

        // ---- O += P * V ----
        const uint32_t* Vb = Vsb[cur];
#pragma unroll
        for (int s = 0; s < 8; s++) {
            const int kk = s * 8;
            uint32_t af[4];
            const uint32_t* p = Psu + (mrow + gid) * AST + kk + tig;
            af[0] = p[0];
            af[1] = p[8 * AST];
            af[2] = p[4];
            af[3] = p[8 * AST + 4];
            uint32_t bf[8][2];
#pragma unroll
            for (int ni = 0; ni < 8; ni++) {
                const uint32_t* q = Vb + (kk + tig) * AST + ni * 8 + gid;
                bf[ni][0] = q[0];
                bf[ni][1] = q[4 * AST];
            }
#pragma unroll
            for (int ni = 0; ni < 8; ni++)
                mma8(o[ni], af, bf[ni]);
        }
        __syncthreads();
    }

    // ---- finalize: divide by l, tf32-round (feeds O-proj), store ----
    {
        const float inv0 = 1.f / l0;
        const float inv1 = 1.f / l1;
        const int r0 = q0 + mrow + gid;
        uint32_t* Ou = (uint32_t*)(Og + base);
#pragma unroll
        for (int ni = 0; ni < 8; ni++) {
            const int cc = ni * 8 + 2 * tig;
            uint2 oa, ob;
            oa.x = tf32r(o[ni][0] * inv0);
            oa.y = tf32r(o[ni][1] * inv0);
            ob.x = tf32r(o[ni][2] * inv1);
            ob.y = tf32r(o[ni][3] * inv1);
            *reinterpret_cast<uint2*>(Ou + (size_t)r0 * HDc + cc) = oa;
            *reinterpret_cast<uint2*>(Ou + (size_t)(r0 + 8) * HDc + cc) = ob;
        }
    }
}

// ---------------------------------------------------------------------------
extern "C" void kernel_launch(void* const* d_in, const int* in_sizes, int n_in,
                              void* d_out, int out_size)
{
    const float* q  = (const float*)d_in[0];
    const float* k  = (const float*)d_in[1];
    const float* v  = (const float*)d_in[2];
    // d_in[3] = mask (tril; causality applied analytically)
    const float* Wq = (const float*)d_in[4];
    const float* bq = (const float*)d_in[5];
    const float* Wk = (const float*)d_in[6];
    const float* bk = (const float*)d_in[7];
    const float* Wv = (const float*)d_in[8];
    const float* bv = (const float*)d_in[9];
    const float* Wo = (const float*)d_in[10];
    const float* bo = (const float*)d_in[11];
    float* out = (float*)d_out;

    float *qh, *kh, *vh, *ao, *qt, *kt, *vt, *wq, *wk, *wv, *wo;
    cudaGetSymbolAddress((void**)&qh, g_qh);
    cudaGetSymbolAddress((void**)&kh, g_kh);
    cudaGetSymbolAddress((void**)&vh, g_vh);
    cudaGetSymbolAddress((void**)&ao, g_ao);
    cudaGetSymbolAddress((void**)&qt, g_qt);
    cudaGetSymbolAddress((void**)&kt, g_kt);
    cudaGetSymbolAddress((void**)&vt, g_vt);
    cudaGetSymbolAddress((void**)&wq, g_wq);
    cudaGetSymbolAddress((void**)&wk, g_wk);
    cudaGetSymbolAddress((void**)&wv, g_wv);
    cudaGetSymbolAddress((void**)&wo, g_wo);

    static int cfg = 0;
    if (!cfg) {
        cudaFuncSetAttribute(qkv_proj,
            cudaFuncAttributeMaxDynamicSharedMemorySize, PROJ_SMEM);
        cudaFuncSetAttribute(o_proj,
            cudaFuncAttributeMaxDynamicSharedMemorySize, PROJ_SMEM);
        cudaFuncSetAttribute(attn2,
            cudaFuncAttributeMaxDynamicSharedMemorySize, ATT_SMEM);
        cfg = 1;
    }

    // Pre-round inputs and weights to tf32 (RNA)
    const int n4_in = Mrows * DIMd / 4;   // 1048576
    const int n4_w  = DIMd * DIMd / 4;    // 262144
    cvt_tf32<<<(n4_in + 255) / 256, 256>>>((const float4*)q, (float4*)qt, n4_in);
    cvt_tf32<<<(n4_in + 255) / 256, 256>>>((const float4*)k, (float4*)kt, n4_in);
    cvt_tf32<<<(n4_in + 255) / 256, 256>>>((const float4*)v, (float4*)vt, n4_in);
    cvt_tf32<<<(n4_w + 255) / 256, 256>>>((const float4*)Wq, (float4*)wq, n4_w);
    cvt_tf32<<<(n4_w + 255) / 256, 256>>>((const float4*)Wk, (float4*)wk, n4_w);
    cvt_tf32<<<(n4_w + 255) / 256, 256>>>((const float4*)Wv, (float4*)wv, n4_w);
    cvt_tf32<<<(n4_w + 255) / 256, 256>>>((const float4*)Wo, (float4*)wo, n4_w);

    // Fused QKV projections (Q pre-scaled by ATTN_SCALE in epilogue)
    qkv_proj<<<dim3(DIMd / 128, Mrows / 128, 3), 256, PROJ_SMEM>>>(
        qt, kt, vt, wq, wk, wv, bq, bk, bv, qh, kh, vh);

    // Attention
    attn2<<<dim3(Nn / 64, Bb * Hh), 128, ATT_SMEM>>>(qh, kh, vh, ao);

    // Output projection
    o_proj<<<dim3(DIMd / 128, Mrows / 128), 256, PROJ_SMEM>>>(ao, wo, bo, out);
}